// round 10
// baseline (speedup 1.0000x reference)
#include <cuda_runtime.h>
#include <cuda_fp16.h>
#include <math.h>

#define NPTS   524288
#define NLVL   16
#define TSIZE  (1 << 19)

// density weights (fp32) shared layout
#define OFF_W1 0        // [32,64]  2048
#define OFF_B1 2048     // [64]
#define OFF_W2 2112     // [64,16]  1024
#define OFF_B2 3136     // [16]
#define DW_TOTAL 3152
// head weights
#define OFF_W5 0        // [64,3] 192
#define OFF_B5 192      // [3]
#define OFF_B4 195      // [64]
#define HW_TOTAL 259

#define A_STRIDE_B  112   // 48 halfs padded to 56 (112B)
#define W3_STRIDE_B 112
#define W4_STRIDE_B 144

// packed f32x2 helpers
#define FMA2(d, a, b, c) \
    asm("fma.rn.f32x2 %0, %1, %2, %3;" : "=l"(d) : "l"(a), "l"(b), "l"(c))
#define PACK2(d, lo, hi) \
    asm("mov.b64 %0, {%1, %2};" : "=l"(d) : "f"(lo), "f"(hi))
#define UNPACK2(lo, hi, v) \
    asm("mov.b64 {%0, %1}, %2;" : "=f"(lo), "=f"(hi) : "l"(v))
typedef unsigned long long u64;

static __device__ __forceinline__ unsigned smem_u32(const void* p) {
    unsigned a;
    asm("{ .reg .u64 t; cvta.to.shared.u64 t, %1; cvt.u32.u64 %0, t; }" : "=r"(a) : "l"(p));
    return a;
}

#define LDMATRIX_X4(r0, r1, r2, r3, addr) \
    asm volatile("ldmatrix.sync.aligned.m8n8.x4.shared.b16 {%0,%1,%2,%3}, [%4];" \
        : "=r"(r0), "=r"(r1), "=r"(r2), "=r"(r3) : "r"(addr))

#define MMA16816(c, a, b0v, b1v) \
    asm volatile("mma.sync.aligned.m16n8k16.row.col.f32.f16.f16.f32 " \
        "{%0,%1,%2,%3}, {%4,%5,%6,%7}, {%8,%9}, {%0,%1,%2,%3};" \
        : "+f"((c)[0]), "+f"((c)[1]), "+f"((c)[2]), "+f"((c)[3]) \
        : "r"((a)[0]), "r"((a)[1]), "r"((a)[2]), "r"((a)[3]), "r"(b0v), "r"(b1v))

// feature scratch, chunk-major: g_feat[c * NPTS + n] holds feat[4c..4c+3] of point n
__device__ float4 g_feat[8 * NPTS];

// ======================= Kernel A: hash-grid encode =======================
__global__ __launch_bounds__(256, 3) void encode_kernel(
    const float* __restrict__ pos,
    const float* __restrict__ tables)
{
    const int i = blockIdx.x * 256 + threadIdx.x;

    const float px = pos[3 * i + 0];
    const float py = pos[3 * i + 1];
    const float pz = pos[3 * i + 2];

    float feat[32];
#pragma unroll
    for (int l = 0; l < NLVL; l++) {
        const float res = (float)(16 << l);      // exact: growth factor b == 2.0
        const float fx = px * res, fy = py * res, fz = pz * res;
        const float bx = floorf(fx), by = floorf(fy), bz = floorf(fz);
        const int ix = (int)bx, iy = (int)by, iz = (int)bz;
        const float wx = fx - bx, wy = fy - by, wz = fz - bz;
        const float2* __restrict__ tab =
            reinterpret_cast<const float2*>(tables) + (size_t)l * TSIZE;

        float f0 = 0.f, f1 = 0.f;
#pragma unroll
        for (int c = 0; c < 8; c++) {
            const int oi = (c >> 2) & 1, oj = (c >> 1) & 1, ok = c & 1;
            unsigned h = (unsigned)(ix + oi) * 1u
                       ^ (unsigned)(iy + oj) * 2654435761u
                       ^ (unsigned)(iz + ok) * 805459861u;
            h &= (TSIZE - 1);
            const float2 e = __ldg(tab + h);
            const float cw = (oi ? wx : 1.f - wx)
                           * (oj ? wy : 1.f - wy)
                           * (ok ? wz : 1.f - wz);
            f0 = fmaf(e.x, cw, f0);
            f1 = fmaf(e.y, cw, f1);
        }
        feat[2 * l + 0] = f0;
        feat[2 * l + 1] = f1;
    }

#pragma unroll
    for (int c = 0; c < 8; c++)
        g_feat[c * NPTS + i] = make_float4(feat[4 * c + 0], feat[4 * c + 1],
                                           feat[4 * c + 2], feat[4 * c + 3]);
}

// ============== Kernel B: density fp32 + SH + HMMA color + heads ==============
__global__ __launch_bounds__(128, 4) void mlp_hmma_kernel(
    const float* __restrict__ dirv,
    const float* __restrict__ W1, const float* __restrict__ B1,
    const float* __restrict__ W2, const float* __restrict__ B2,
    const float* __restrict__ W3, const float* __restrict__ B3,
    const float* __restrict__ W4, const float* __restrict__ B4,
    const float* __restrict__ W5, const float* __restrict__ B5,
    float* __restrict__ out)
{
    __shared__ __align__(16) unsigned char sA[128 * A_STRIDE_B];
    __shared__ __align__(16) unsigned char sW3T[64 * W3_STRIDE_B];
    __shared__ __align__(16) unsigned char sW4T[64 * W4_STRIDE_B];
    __shared__ float sDW[DW_TOTAL];
    __shared__ float sHW[HW_TOTAL];

    const int tid  = threadIdx.x;
    const int lane = tid & 31;
    const int w    = tid >> 5;
    const int g    = lane >> 2;
    const int t4   = lane & 3;

    for (int t = tid; t < 2048; t += 128) sDW[OFF_W1 + t] = W1[t];
    for (int t = tid; t < 64;   t += 128) sDW[OFF_B1 + t] = B1[t];
    for (int t = tid; t < 1024; t += 128) sDW[OFF_W2 + t] = W2[t];
    for (int t = tid; t < 16;   t += 128) sDW[OFF_B2 + t] = B2[t];
    for (int t = tid; t < 192;  t += 128) sHW[OFF_W5 + t] = W5[t];
    for (int t = tid; t < 3;    t += 128) sHW[OFF_B5 + t] = B5[t];
    for (int t = tid; t < 64;   t += 128) sHW[OFF_B4 + t] = B4[t];

    for (int idx = tid; idx < 64 * 56; idx += 128) {
        const int n = idx / 56, k = idx % 56;
        float v = 0.0f;
        if (k < 41) v = W3[k * 64 + n];
        else if (k == 41) v = B3[n];
        *reinterpret_cast<__half*>(sW3T + n * W3_STRIDE_B + k * 2) = __float2half_rn(v);
    }
    for (int idx = tid; idx < 64 * 72; idx += 128) {
        const int n = idx / 72, k = idx % 72;
        const float v = (k < 64) ? W4[k * 64 + n] : 0.0f;
        *reinterpret_cast<__half*>(sW4T + n * W4_STRIDE_B + k * 2) = __float2half_rn(v);
    }
    __syncthreads();

    const int i = blockIdx.x * 128 + tid;

    // ---- load features from scratch (coalesced, chunk-major) ----
    float feat[32];
#pragma unroll
    for (int c = 0; c < 8; c++) {
        const float4 f = g_feat[c * NPTS + i];
        feat[4 * c + 0] = f.x; feat[4 * c + 1] = f.y;
        feat[4 * c + 2] = f.z; feat[4 * c + 3] = f.w;
    }

    // ------- density MLP (fp32, packed f32x2): 32 -> 64 relu -> 16 -------
    u64 den[8];
#pragma unroll
    for (int j = 0; j < 8; j++) PACK2(den[j], sDW[OFF_B2 + 2 * j], sDW[OFF_B2 + 2 * j + 1]);
    {
        const ulonglong2* __restrict__ W1v = reinterpret_cast<const ulonglong2*>(sDW + OFF_W1);
        const ulonglong2* __restrict__ W2v = reinterpret_cast<const ulonglong2*>(sDW + OFF_W2);
#pragma unroll
        for (int cch = 0; cch < 4; cch++) {
            u64 yc[8];
#pragma unroll
            for (int j = 0; j < 8; j++)
                PACK2(yc[j], sDW[OFF_B1 + cch * 16 + 2 * j], sDW[OFF_B1 + cch * 16 + 2 * j + 1]);
#pragma unroll
            for (int k = 0; k < 32; k++) {
                u64 vv; PACK2(vv, feat[k], feat[k]);
#pragma unroll
                for (int j2 = 0; j2 < 4; j2++) {
                    const ulonglong2 wv = W1v[k * 16 + cch * 4 + j2];
                    FMA2(yc[2 * j2 + 0], vv, wv.x, yc[2 * j2 + 0]);
                    FMA2(yc[2 * j2 + 1], vv, wv.y, yc[2 * j2 + 1]);
                }
            }
#pragma unroll
            for (int k2 = 0; k2 < 8; k2++) {
                float a, b; UNPACK2(a, b, yc[k2]);
                a = fmaxf(a, 0.f); b = fmaxf(b, 0.f);
                u64 va; PACK2(va, a, a);
                u64 vb; PACK2(vb, b, b);
                const int kk = cch * 16 + 2 * k2;
#pragma unroll
                for (int j2 = 0; j2 < 4; j2++) {
                    const ulonglong2 wa = W2v[kk * 4 + j2];
                    FMA2(den[2 * j2 + 0], va, wa.x, den[2 * j2 + 0]);
                    FMA2(den[2 * j2 + 1], va, wa.y, den[2 * j2 + 1]);
                }
#pragma unroll
                for (int j2 = 0; j2 < 4; j2++) {
                    const ulonglong2 wb = W2v[(kk + 1) * 4 + j2];
                    FMA2(den[2 * j2 + 0], vb, wb.x, den[2 * j2 + 0]);
                    FMA2(den[2 * j2 + 1], vb, wb.y, den[2 * j2 + 1]);
                }
            }
        }
    }
    float den_s[16];
#pragma unroll
    for (int j = 0; j < 8; j++) UNPACK2(den_s[2 * j], den_s[2 * j + 1], den[j]);
    out[3 * NPTS + i] = fmaxf(den_s[15], 0.f);   // sigma: exact fp32

    // ---------------- SH degree-4 (25) ----------------
    float sh[25];
    {
        const float x = dirv[3 * i + 0];
        const float yv = dirv[3 * i + 1];
        const float z = dirv[3 * i + 2];
        const float x2 = x * x, y2 = yv * yv, z2 = z * z;
        const float xy = x * yv, xz = x * z, yz = yv * z;
        const float x4 = x2 * x2, y4 = y2 * y2;
        sh[0] = 0.28209479177387814f;
        const float c1 = 0.4886025119029199f;
        sh[1] = -c1 * yv; sh[2] = c1 * z; sh[3] = -c1 * x;
        const float sub = 0.31539156525252005f;
        const float v1 = 0.5462742152960396f, v2 = 1.0925484305920792f, v3 = 0.9461746957575601f;
        sh[4] = v2 * xy; sh[5] = -v2 * yz; sh[6] = v3 * z2 - sub; sh[7] = -v2 * xz;
        sh[8] = v1 * x2 - v1 * y2;
        const float w1c = 1.445305721320277f, w2c = 2.890611442640554f;
        const float w3c = 0.5900435899266435f, w4c = 0.304697199642977f;
        sh[9]  = -w3c * yv * (3.0f * x2 - y2);
        sh[10] =  w2c * xy * z;
        sh[11] =  w4c * yv * (1.5f - 7.5f * z2);
        sh[12] =  1.24392110863372f * z * (1.5f * z2 - 0.5f) - 0.497568443453487f * z;
        sh[13] =  w4c * x * (1.5f - 7.5f * z2);
        sh[14] =  w1c * z * (x2 - y2);
        sh[15] = -w3c * x * (x2 - 3.0f * y2);
        sh[16] =  2.5033429417967f * xy * (x2 - y2);
        sh[17] = -1.77013076977993f * yz * (3.0f * x2 - y2);
        sh[18] =  0.126156626101008f * xy * (52.5f * z2 - 7.5f);
        sh[19] =  0.267618617422916f * yv * (2.33333333333333f * z * (1.5f - 7.5f * z2) + 4.0f * z);
        sh[20] =  1.48099765681286f * z * (1.66666666666667f * z * (1.5f * z2 - 0.5f)
                                           - 0.666666666666667f * z)
                  - 0.952069922236839f * z2 + 0.317356640745613f;
        sh[21] =  0.267618617422916f * x * (2.33333333333333f * z * (1.5f - 7.5f * z2) + 4.0f * z);
        sh[22] =  0.063078313050504f * (x2 - y2) * (52.5f * z2 - 7.5f);
        sh[23] = -1.77013076977993f * xz * (x2 - 3.0f * y2);
        sh[24] = -3.75501441269506f * x2 * y2 + 0.625835735449176f * x4 + 0.625835735449176f * y4;
    }

    // ---- stage A1 row (48 f16) ----
    {
        __half v[48];
#pragma unroll
        for (int k = 0; k < 16; k++) v[k] = __float2half_rn(den_s[k]);
#pragma unroll
        for (int k = 0; k < 25; k++) v[16 + k] = __float2half_rn(sh[k]);
        v[41] = __float2half_rn(1.0f);
#pragma unroll
        for (int k = 42; k < 48; k++) v[k] = __float2half_rn(0.0f);
        const uint4* vv = reinterpret_cast<const uint4*>(v);
        unsigned char* row = sA + tid * A_STRIDE_B;
#pragma unroll
        for (int q = 0; q < 6; q++)
            *reinterpret_cast<uint4*>(row + q * 16) = vv[q];
    }
    __syncwarp();

    // ---- A1 fragments via ldmatrix ----
    unsigned a1f[2][3][4];
    {
        const unsigned base = smem_u32(sA);
        const int m = lane >> 3, r = lane & 7;
#pragma unroll
        for (int mt = 0; mt < 2; mt++) {
#pragma unroll
            for (int kk = 0; kk < 3; kk++) {
                const int row = w * 32 + mt * 16 + (m & 1) * 8 + r;
                const unsigned addr = base + row * A_STRIDE_B + kk * 32 + (m >> 1) * 16;
                LDMATRIX_X4(a1f[mt][kk][0], a1f[mt][kk][1], a1f[mt][kk][2], a1f[mt][kk][3], addr);
            }
        }
    }

    // ---- layer 1 MMA ----
    float acc1[2][8][4];
#pragma unroll
    for (int mt = 0; mt < 2; mt++)
#pragma unroll
        for (int nt = 0; nt < 8; nt++)
#pragma unroll
            for (int c = 0; c < 4; c++) acc1[mt][nt][c] = 0.f;
    {
        const unsigned char* bbase = sW3T + (g * W3_STRIDE_B) + 4 * t4;
#pragma unroll
        for (int nt = 0; nt < 8; nt++) {
#pragma unroll
            for (int kk = 0; kk < 3; kk++) {
                const unsigned char* p = bbase + nt * 8 * W3_STRIDE_B + kk * 32;
                const unsigned b0v = *reinterpret_cast<const unsigned*>(p);
                const unsigned b1v = *reinterpret_cast<const unsigned*>(p + 16);
                MMA16816(acc1[0][nt], a1f[0][kk], b0v, b1v);
                MMA16816(acc1[1][nt], a1f[1][kk], b0v, b1v);
            }
        }
    }

    // ---- relu + repack to A2 fragments (registers only) ----
    unsigned a2f[2][4][4];
#pragma unroll
    for (int mt = 0; mt < 2; mt++) {
#pragma unroll
        for (int kk = 0; kk < 4; kk++) {
            const float* cA = acc1[mt][2 * kk];
            const float* cB = acc1[mt][2 * kk + 1];
            __half2 h0 = __floats2half2_rn(fmaxf(cA[0], 0.f), fmaxf(cA[1], 0.f));
            __half2 h1 = __floats2half2_rn(fmaxf(cA[2], 0.f), fmaxf(cA[3], 0.f));
            __half2 h2 = __floats2half2_rn(fmaxf(cB[0], 0.f), fmaxf(cB[1], 0.f));
            __half2 h3 = __floats2half2_rn(fmaxf(cB[2], 0.f), fmaxf(cB[3], 0.f));
            a2f[mt][kk][0] = *reinterpret_cast<unsigned*>(&h0);
            a2f[mt][kk][1] = *reinterpret_cast<unsigned*>(&h1);
            a2f[mt][kk][2] = *reinterpret_cast<unsigned*>(&h2);
            a2f[mt][kk][3] = *reinterpret_cast<unsigned*>(&h3);
        }
    }

    // ---- layer 2 MMA ----
    float acc2[2][8][4];
#pragma unroll
    for (int mt = 0; mt < 2; mt++)
#pragma unroll
        for (int nt = 0; nt < 8; nt++)
#pragma unroll
            for (int c = 0; c < 4; c++) acc2[mt][nt][c] = 0.f;
    {
        const unsigned char* bbase = sW4T + (g * W4_STRIDE_B) + 4 * t4;
#pragma unroll
        for (int nt = 0; nt < 8; nt++) {
#pragma unroll
            for (int kk = 0; kk < 4; kk++) {
                const unsigned char* p = bbase + nt * 8 * W4_STRIDE_B + kk * 32;
                const unsigned b0v = *reinterpret_cast<const unsigned*>(p);
                const unsigned b1v = *reinterpret_cast<const unsigned*>(p + 16);
                MMA16816(acc2[0][nt], a2f[0][kk], b0v, b1v);
                MMA16816(acc2[1][nt], a2f[1][kk], b0v, b1v);
            }
        }
    }

    // ---- head: +b4, relu, 64->3, lane-group reduce, sigmoid ----
    {
        float pr[4][3];
#pragma unroll
        for (int q = 0; q < 4; q++) { pr[q][0] = 0.f; pr[q][1] = 0.f; pr[q][2] = 0.f; }
#pragma unroll
        for (int nt = 0; nt < 8; nt++) {
#pragma unroll
            for (int j = 0; j < 2; j++) {
                const int col = nt * 8 + 2 * t4 + j;
                const float b4v = sHW[OFF_B4 + col];
                const float w50 = sHW[OFF_W5 + col * 3 + 0];
                const float w51 = sHW[OFF_W5 + col * 3 + 1];
                const float w52 = sHW[OFF_W5 + col * 3 + 2];
#pragma unroll
                for (int mt = 0; mt < 2; mt++) {
#pragma unroll
                    for (int hh = 0; hh < 2; hh++) {
                        const float hv = fmaxf(acc2[mt][nt][2 * hh + j] + b4v, 0.f);
                        pr[mt * 2 + hh][0] = fmaf(hv, w50, pr[mt * 2 + hh][0]);
                        pr[mt * 2 + hh][1] = fmaf(hv, w51, pr[mt * 2 + hh][1]);
                        pr[mt * 2 + hh][2] = fmaf(hv, w52, pr[mt * 2 + hh][2]);
                    }
                }
            }
        }
#pragma unroll
        for (int q = 0; q < 4; q++) {
#pragma unroll
            for (int c = 0; c < 3; c++) {
                float v = pr[q][c];
                v += __shfl_xor_sync(0xffffffffu, v, 1);
                v += __shfl_xor_sync(0xffffffffu, v, 2);
                pr[q][c] = v;
            }
        }
        if (t4 == 0) {
            const float b50 = sHW[OFF_B5 + 0], b51 = sHW[OFF_B5 + 1], b52 = sHW[OFF_B5 + 2];
#pragma unroll
            for (int mt = 0; mt < 2; mt++) {
#pragma unroll
                for (int hh = 0; hh < 2; hh++) {
                    const int p = blockIdx.x * 128 + w * 32 + mt * 16 + hh * 8 + g;
                    const int q = mt * 2 + hh;
                    out[3 * p + 0] = 1.0f / (1.0f + __expf(-(pr[q][0] + b50)));
                    out[3 * p + 1] = 1.0f / (1.0f + __expf(-(pr[q][1] + b51)));
                    out[3 * p + 2] = 1.0f / (1.0f + __expf(-(pr[q][2] + b52)));
                }
            }
        }
    }
}

extern "C" void kernel_launch(void* const* d_in, const int* in_sizes, int n_in,
                              void* d_out, int out_size)
{
    const float* pos    = (const float*)d_in[0];
    const float* dirv   = (const float*)d_in[1];
    const float* tables = (const float*)d_in[2];
    const float* W1 = (const float*)d_in[3];
    const float* B1 = (const float*)d_in[4];
    const float* W2 = (const float*)d_in[5];
    const float* B2 = (const float*)d_in[6];
    const float* W3 = (const float*)d_in[7];
    const float* B3 = (const float*)d_in[8];
    const float* W4 = (const float*)d_in[9];
    const float* B4 = (const float*)d_in[10];
    const float* W5 = (const float*)d_in[11];
    const float* B5 = (const float*)d_in[12];
    float* out = (float*)d_out;

    encode_kernel<<<NPTS / 256, 256>>>(pos, tables);
    mlp_hmma_kernel<<<NPTS / 128, 128>>>(
        dirv, W1, B1, W2, B2, W3, B3, W4, B4, W5, B5, out);
}

// round 12
// speedup vs baseline: 1.0382x; 1.0382x over previous
#include <cuda_runtime.h>
#include <cuda_fp16.h>
#include <math.h>

#define NPTS   524288
#define NLVL   16
#define TSIZE  (1 << 19)

// constants in shared (floats)
#define OFF_W5 0        // [64,3] 192
#define OFF_B5 192      // [3]
#define OFF_B4 195      // [64]
#define OFF_B2 259      // [16]
#define OFF_B1 275      // [64]
#define OFF_W2C15 339   // [64]  W2[:,15] fp32 (sigma column)
#define HW_TOTAL 403

#define A_STRIDE_B  144   // 72-half rows; r*36 words mod 32 = 4r -> ldmatrix conflict-free
#define W1_STRIDE_B 144
#define W2_STRIDE_B 144
#define W3_STRIDE_B 112
#define W4_STRIDE_B 144

#define SCALE_S 4096.0f
#define INV_S   (1.0f / 4096.0f)

typedef unsigned long long u64;

static __device__ __forceinline__ unsigned smem_u32(const void* p) {
    unsigned a;
    asm("{ .reg .u64 t; cvta.to.shared.u64 t, %1; cvt.u32.u64 %0, t; }" : "=r"(a) : "l"(p));
    return a;
}

#define LDMATRIX_X4(r0, r1, r2, r3, addr) \
    asm volatile("ldmatrix.sync.aligned.m8n8.x4.shared.b16 {%0,%1,%2,%3}, [%4];" \
        : "=r"(r0), "=r"(r1), "=r"(r2), "=r"(r3) : "r"(addr))

#define MMA16816(c, a, b0v, b1v) \
    asm volatile("mma.sync.aligned.m16n8k16.row.col.f32.f16.f16.f32 " \
        "{%0,%1,%2,%3}, {%4,%5,%6,%7}, {%8,%9}, {%0,%1,%2,%3};" \
        : "+f"((c)[0]), "+f"((c)[1]), "+f"((c)[2]), "+f"((c)[3]) \
        : "r"((a)[0]), "r"((a)[1]), "r"((a)[2]), "r"((a)[3]), "r"(b0v), "r"(b1v))

// feature scratch, chunk-major: g_feat[c * NPTS + n] holds feat[4c..4c+3] of point n
__device__ float4 g_feat[8 * NPTS];

// ======================= Kernel A: hash-grid encode =======================
__global__ __launch_bounds__(256, 3) void encode_kernel(
    const float* __restrict__ pos,
    const float* __restrict__ tables)
{
    const int i = blockIdx.x * 256 + threadIdx.x;

    const float px = pos[3 * i + 0];
    const float py = pos[3 * i + 1];
    const float pz = pos[3 * i + 2];

    float feat[32];
#pragma unroll
    for (int l = 0; l < NLVL; l++) {
        const float res = (float)(16 << l);      // exact: growth factor b == 2.0
        const float fx = px * res, fy = py * res, fz = pz * res;
        const float bx = floorf(fx), by = floorf(fy), bz = floorf(fz);
        const int ix = (int)bx, iy = (int)by, iz = (int)bz;
        const float wx = fx - bx, wy = fy - by, wz = fz - bz;
        const float2* __restrict__ tab =
            reinterpret_cast<const float2*>(tables) + (size_t)l * TSIZE;

        float f0 = 0.f, f1 = 0.f;
#pragma unroll
        for (int c = 0; c < 8; c++) {
            const int oi = (c >> 2) & 1, oj = (c >> 1) & 1, ok = c & 1;
            unsigned h = (unsigned)(ix + oi) * 1u
                       ^ (unsigned)(iy + oj) * 2654435761u
                       ^ (unsigned)(iz + ok) * 805459861u;
            h &= (TSIZE - 1);
            const float2 e = __ldg(tab + h);
            const float cw = (oi ? wx : 1.f - wx)
                           * (oj ? wy : 1.f - wy)
                           * (ok ? wz : 1.f - wz);
            f0 = fmaf(e.x, cw, f0);
            f1 = fmaf(e.y, cw, f1);
        }
        feat[2 * l + 0] = f0;
        feat[2 * l + 1] = f1;
    }

#pragma unroll
    for (int c = 0; c < 8; c++)
        g_feat[c * NPTS + i] = make_float4(feat[4 * c + 0], feat[4 * c + 1],
                                           feat[4 * c + 2], feat[4 * c + 3]);
}

// ============== Kernel B: all-HMMA MLPs + fp32 sigma path ==============
__global__ __launch_bounds__(128, 4) void mlp_hmma_kernel(
    const float* __restrict__ dirv,
    const float* __restrict__ W1, const float* __restrict__ B1,
    const float* __restrict__ W2, const float* __restrict__ B2,
    const float* __restrict__ W3, const float* __restrict__ B3,
    const float* __restrict__ W4, const float* __restrict__ B4,
    const float* __restrict__ W5, const float* __restrict__ B5,
    float* __restrict__ out)
{
    __shared__ __align__(16) unsigned char sA[128 * A_STRIDE_B];     // A0 (hi|lo), later A1
    __shared__ __align__(16) unsigned char sW1T[64 * W1_STRIDE_B];   // [Whi | Whi] rows n
    __shared__ __align__(16) unsigned char sW2T[16 * W2_STRIDE_B];   // W2^T (K=64)
    __shared__ __align__(16) unsigned char sW3T[64 * W3_STRIDE_B];   // W3^T + B3 col (K=48)
    __shared__ __align__(16) unsigned char sW4T[64 * W4_STRIDE_B];   // W4^T (K=64)
    __shared__ float sHW[HW_TOTAL];

    const int tid  = threadIdx.x;
    const int lane = tid & 31;
    const int w    = tid >> 5;
    const int g    = lane >> 2;
    const int t4   = lane & 3;

    for (int t = tid; t < 192; t += 128) sHW[OFF_W5 + t] = W5[t];
    for (int t = tid; t < 3;   t += 128) sHW[OFF_B5 + t] = B5[t];
    for (int t = tid; t < 64;  t += 128) sHW[OFF_B4 + t] = B4[t];
    for (int t = tid; t < 16;  t += 128) sHW[OFF_B2 + t] = B2[t];
    for (int t = tid; t < 64;  t += 128) sHW[OFF_B1 + t] = B1[t];
    for (int t = tid; t < 64;  t += 128) sHW[OFF_W2C15 + t] = W2[t * 16 + 15];

    // W1T rows [n][c]: c<32 -> f16(W1[c][n]), 32<=c<64 -> f16(W1[c-32][n]) (dup for lo pass)
    for (int idx = tid; idx < 64 * 72; idx += 128) {
        const int n = idx / 72, k = idx % 72;
        float v = 0.0f;
        if (k < 32) v = W1[k * 64 + n];
        else if (k < 64) v = W1[(k - 32) * 64 + n];
        *reinterpret_cast<__half*>(sW1T + n * W1_STRIDE_B + k * 2) = __float2half_rn(v);
    }
    // W2^T rows [n][k], K=64 padded to 72
    for (int idx = tid; idx < 16 * 72; idx += 128) {
        const int n = idx / 72, k = idx % 72;
        const float v = (k < 64) ? W2[k * 16 + n] : 0.0f;
        *reinterpret_cast<__half*>(sW2T + n * W2_STRIDE_B + k * 2) = __float2half_rn(v);
    }
    // W3^T rows: k<41 -> W3, k==41 -> B3, else 0
    for (int idx = tid; idx < 64 * 56; idx += 128) {
        const int n = idx / 56, k = idx % 56;
        float v = 0.0f;
        if (k < 41) v = W3[k * 64 + n];
        else if (k == 41) v = B3[n];
        *reinterpret_cast<__half*>(sW3T + n * W3_STRIDE_B + k * 2) = __float2half_rn(v);
    }
    // W4^T rows, K=64 padded to 72
    for (int idx = tid; idx < 64 * 72; idx += 128) {
        const int n = idx / 72, k = idx % 72;
        const float v = (k < 64) ? W4[k * 64 + n] : 0.0f;
        *reinterpret_cast<__half*>(sW4T + n * W4_STRIDE_B + k * 2) = __float2half_rn(v);
    }
    __syncthreads();

    const int i = blockIdx.x * 128 + tid;
    const int m = lane >> 3, r = lane & 7;
    const unsigned sAbase = smem_u32(sA);

    // ---- stage A0 row: [fh(32) | fl(32) | 0..71] with S=4096 scaling ----
    {
        __half v[72];
#pragma unroll
        for (int c = 0; c < 8; c++) {
            const float4 f = g_feat[c * NPTS + i];
            const float fv[4] = { f.x, f.y, f.z, f.w };
#pragma unroll
            for (int j = 0; j < 4; j++) {
                const float fs = fv[j] * SCALE_S;
                const __half fh = __float2half_rn(fs);
                v[4 * c + j]      = fh;
                v[32 + 4 * c + j] = __float2half_rn(fs - __half2float(fh));
            }
        }
#pragma unroll
        for (int k = 64; k < 72; k++) v[k] = __float2half_rn(0.0f);
        const uint4* vv = reinterpret_cast<const uint4*>(v);
        unsigned char* row = sA + tid * A_STRIDE_B;
#pragma unroll
        for (int q = 0; q < 9; q++)
            *reinterpret_cast<uint4*>(row + q * 16) = vv[q];
    }
    __syncwarp();

    // ---- density layer 1 (HMMA, exact A): acc = 4096 * feat . W1hi ----
    unsigned ayf[2][4][4];
    float prS[4];
#pragma unroll
    for (int q = 0; q < 4; q++) prS[q] = 0.f;

#pragma unroll
    for (int mt = 0; mt < 2; mt++) {
        unsigned af[4][4];
#pragma unroll
        for (int kk = 0; kk < 4; kk++) {
            const int row = w * 32 + mt * 16 + (m & 1) * 8 + r;
            const unsigned addr = sAbase + row * A_STRIDE_B + kk * 32 + (m >> 1) * 16;
            LDMATRIX_X4(af[kk][0], af[kk][1], af[kk][2], af[kk][3], addr);
        }
        float acc[8][4];
#pragma unroll
        for (int nt = 0; nt < 8; nt++)
#pragma unroll
            for (int c = 0; c < 4; c++) acc[nt][c] = 0.f;
        {
            const unsigned char* bbase = sW1T + (g * W1_STRIDE_B) + 4 * t4;
#pragma unroll
            for (int nt = 0; nt < 8; nt++)
#pragma unroll
                for (int kk = 0; kk < 4; kk++) {
                    const unsigned char* p = bbase + nt * 8 * W1_STRIDE_B + kk * 32;
                    const unsigned b0v = *reinterpret_cast<const unsigned*>(p);
                    const unsigned b1v = *reinterpret_cast<const unsigned*>(p + 16);
                    MMA16816(acc[nt], af[kk], b0v, b1v);
                }
        }
        // epilogue: y = relu(acc/4096 + b1); sigma fp32 partial; pack f16 frags
#pragma unroll
        for (int kk = 0; kk < 4; kk++) {
            const float* cA = acc[2 * kk];
            const float* cB = acc[2 * kk + 1];
            const int colA = (2 * kk) * 8 + 2 * t4;
            const int colB = colA + 8;
            const float y00 = fmaxf(fmaf(cA[0], INV_S, sHW[OFF_B1 + colA]),     0.f);
            const float y01 = fmaxf(fmaf(cA[1], INV_S, sHW[OFF_B1 + colA + 1]), 0.f);
            const float y10 = fmaxf(fmaf(cA[2], INV_S, sHW[OFF_B1 + colA]),     0.f);
            const float y11 = fmaxf(fmaf(cA[3], INV_S, sHW[OFF_B1 + colA + 1]), 0.f);
            const float z00 = fmaxf(fmaf(cB[0], INV_S, sHW[OFF_B1 + colB]),     0.f);
            const float z01 = fmaxf(fmaf(cB[1], INV_S, sHW[OFF_B1 + colB + 1]), 0.f);
            const float z10 = fmaxf(fmaf(cB[2], INV_S, sHW[OFF_B1 + colB]),     0.f);
            const float z11 = fmaxf(fmaf(cB[3], INV_S, sHW[OFF_B1 + colB + 1]), 0.f);
            const float wA0 = sHW[OFF_W2C15 + colA], wA1 = sHW[OFF_W2C15 + colA + 1];
            const float wB0 = sHW[OFF_W2C15 + colB], wB1 = sHW[OFF_W2C15 + colB + 1];
            prS[mt * 2 + 0] += y00 * wA0 + y01 * wA1 + z00 * wB0 + z01 * wB1;
            prS[mt * 2 + 1] += y10 * wA0 + y11 * wA1 + z10 * wB0 + z11 * wB1;
            const __half2 h0 = __floats2half2_rn(y00, y01);
            const __half2 h1 = __floats2half2_rn(y10, y11);
            const __half2 h2 = __floats2half2_rn(z00, z01);
            const __half2 h3 = __floats2half2_rn(z10, z11);
            ayf[mt][kk][0] = *reinterpret_cast<const unsigned*>(&h0);
            ayf[mt][kk][1] = *reinterpret_cast<const unsigned*>(&h1);
            ayf[mt][kk][2] = *reinterpret_cast<const unsigned*>(&h2);
            ayf[mt][kk][3] = *reinterpret_cast<const unsigned*>(&h3);
        }
    }

    // ---- sigma: reduce over t4 group, add b2[15], relu, store (fp32 path) ----
    {
#pragma unroll
        for (int q = 0; q < 4; q++) {
            float v = prS[q];
            v += __shfl_xor_sync(0xffffffffu, v, 1);
            v += __shfl_xor_sync(0xffffffffu, v, 2);
            prS[q] = v;
        }
        if (t4 == 0) {
            const float b2s = sHW[OFF_B2 + 15];
#pragma unroll
            for (int mt = 0; mt < 2; mt++)
#pragma unroll
                for (int ch = 0; ch < 2; ch++) {
                    const int row = w * 32 + mt * 16 + ch * 8 + g;
                    out[3 * NPTS + blockIdx.x * 128 + row] =
                        fmaxf(prS[mt * 2 + ch] + b2s, 0.f);
                }
        }
    }

    // ---- density layer 2 (HMMA f16, color-path den only): den = y x W2 ----
    float accD2[2][2][4];
#pragma unroll
    for (int mt = 0; mt < 2; mt++)
#pragma unroll
        for (int nt = 0; nt < 2; nt++)
#pragma unroll
            for (int c = 0; c < 4; c++) accD2[mt][nt][c] = 0.f;
    {
        const unsigned char* bbase = sW2T + (g * W2_STRIDE_B) + 4 * t4;
#pragma unroll
        for (int nt = 0; nt < 2; nt++)
#pragma unroll
            for (int kk = 0; kk < 4; kk++) {
                const unsigned char* p = bbase + nt * 8 * W2_STRIDE_B + kk * 32;
                const unsigned b0v = *reinterpret_cast<const unsigned*>(p);
                const unsigned b1v = *reinterpret_cast<const unsigned*>(p + 16);
                MMA16816(accD2[0][nt], ayf[0][kk], b0v, b1v);
                MMA16816(accD2[1][nt], ayf[1][kk], b0v, b1v);
            }
    }

    // ---- den + B2 -> f16 into A1 cols 0..15 ----
#pragma unroll
    for (int mt = 0; mt < 2; mt++)
#pragma unroll
        for (int nt = 0; nt < 2; nt++)
#pragma unroll
            for (int ch = 0; ch < 2; ch++) {
                const int row = w * 32 + mt * 16 + ch * 8 + g;
                const int col0 = nt * 8 + 2 * t4;
                const float v0 = accD2[mt][nt][2 * ch + 0] + sHW[OFF_B2 + col0];
                const float v1 = accD2[mt][nt][2 * ch + 1] + sHW[OFF_B2 + col0 + 1];
                const __half2 hv = __floats2half2_rn(v0, v1);
                *reinterpret_cast<__half2*>(sA + row * A_STRIDE_B + col0 * 2) = hv;
            }

    // ---------------- SH degree-4 (25) -> A1 cols 16..47 ----------------
    {
        const float x = dirv[3 * i + 0];
        const float yv = dirv[3 * i + 1];
        const float z = dirv[3 * i + 2];
        const float x2 = x * x, y2 = yv * yv, z2 = z * z;
        const float xy = x * yv, xz = x * z, yz = yv * z;
        const float x4 = x2 * x2, y4 = y2 * y2;
        float sh[25];
        sh[0] = 0.28209479177387814f;
        const float c1 = 0.4886025119029199f;
        sh[1] = -c1 * yv; sh[2] = c1 * z; sh[3] = -c1 * x;
        const float sub = 0.31539156525252005f;
        const float v1 = 0.5462742152960396f, v2 = 1.0925484305920792f, v3 = 0.9461746957575601f;
        sh[4] = v2 * xy; sh[5] = -v2 * yz; sh[6] = v3 * z2 - sub; sh[7] = -v2 * xz;
        sh[8] = v1 * x2 - v1 * y2;
        const float w1c = 1.445305721320277f, w2c = 2.890611442640554f;
        const float w3c = 0.5900435899266435f, w4c = 0.304697199642977f;
        sh[9]  = -w3c * yv * (3.0f * x2 - y2);
        sh[10] =  w2c * xy * z;
        sh[11] =  w4c * yv * (1.5f - 7.5f * z2);
        sh[12] =  1.24392110863372f * z * (1.5f * z2 - 0.5f) - 0.497568443453487f * z;
        sh[13] =  w4c * x * (1.5f - 7.5f * z2);
        sh[14] =  w1c * z * (x2 - y2);
        sh[15] = -w3c * x * (x2 - 3.0f * y2);
        sh[16] =  2.5033429417967f * xy * (x2 - y2);
        sh[17] = -1.77013076977993f * yz * (3.0f * x2 - y2);
        sh[18] =  0.126156626101008f * xy * (52.5f * z2 - 7.5f);
        sh[19] =  0.267618617422916f * yv * (2.33333333333333f * z * (1.5f - 7.5f * z2) + 4.0f * z);
        sh[20] =  1.48099765681286f * z * (1.66666666666667f * z * (1.5f * z2 - 0.5f)
                                           - 0.666666666666667f * z)
                  - 0.952069922236839f * z2 + 0.317356640745613f;
        sh[21] =  0.267618617422916f * x * (2.33333333333333f * z * (1.5f - 7.5f * z2) + 4.0f * z);
        sh[22] =  0.063078313050504f * (x2 - y2) * (52.5f * z2 - 7.5f);
        sh[23] = -1.77013076977993f * xz * (x2 - 3.0f * y2);
        sh[24] = -3.75501441269506f * x2 * y2 + 0.625835735449176f * x4 + 0.625835735449176f * y4;

        __half v[32];
#pragma unroll
        for (int k = 0; k < 25; k++) v[k] = __float2half_rn(sh[k]);
        v[25] = __float2half_rn(1.0f);   // col 41 = bias
#pragma unroll
        for (int k = 26; k < 32; k++) v[k] = __float2half_rn(0.0f);
        const uint4* vv = reinterpret_cast<const uint4*>(v);
        unsigned char* row = sA + tid * A_STRIDE_B + 32;
#pragma unroll
        for (int q = 0; q < 4; q++)
            *reinterpret_cast<uint4*>(row + q * 16) = vv[q];
    }
    __syncwarp();

    // ---- color layer 1 (HMMA): h1 = relu(A1 x W3b) ----
    unsigned a1f[2][3][4];
#pragma unroll
    for (int mt = 0; mt < 2; mt++)
#pragma unroll
        for (int kk = 0; kk < 3; kk++) {
            const int row = w * 32 + mt * 16 + (m & 1) * 8 + r;
            const unsigned addr = sAbase + row * A_STRIDE_B + kk * 32 + (m >> 1) * 16;
            LDMATRIX_X4(a1f[mt][kk][0], a1f[mt][kk][1], a1f[mt][kk][2], a1f[mt][kk][3], addr);
        }

    float acc1[2][8][4];
#pragma unroll
    for (int mt = 0; mt < 2; mt++)
#pragma unroll
        for (int nt = 0; nt < 8; nt++)
#pragma unroll
            for (int c = 0; c < 4; c++) acc1[mt][nt][c] = 0.f;
    {
        const unsigned char* bbase = sW3T + (g * W3_STRIDE_B) + 4 * t4;
#pragma unroll
        for (int nt = 0; nt < 8; nt++)
#pragma unroll
            for (int kk = 0; kk < 3; kk++) {
                const unsigned char* p = bbase + nt * 8 * W3_STRIDE_B + kk * 32;
                const unsigned b0v = *reinterpret_cast<const unsigned*>(p);
                const unsigned b1v = *reinterpret_cast<const unsigned*>(p + 16);
                MMA16816(acc1[0][nt], a1f[0][kk], b0v, b1v);
                MMA16816(acc1[1][nt], a1f[1][kk], b0v, b1v);
            }
    }

    // ---- relu + repack -> A2 fragments ----
    unsigned a2f[2][4][4];
#pragma unroll
    for (int mt = 0; mt < 2; mt++)
#pragma unroll
        for (int kk = 0; kk < 4; kk++) {
            const float* cA = acc1[mt][2 * kk];
            const float* cB = acc1[mt][2 * kk + 1];
            __half2 h0 = __floats2half2_rn(fmaxf(cA[0], 0.f), fmaxf(cA[1], 0.f));
            __half2 h1 = __floats2half2_rn(fmaxf(cA[2], 0.f), fmaxf(cA[3], 0.f));
            __half2 h2 = __floats2half2_rn(fmaxf(cB[0], 0.f), fmaxf(cB[1], 0.f));
            __half2 h3 = __floats2half2_rn(fmaxf(cB[2], 0.f), fmaxf(cB[3], 0.f));
            a2f[mt][kk][0] = *reinterpret_cast<unsigned*>(&h0);
            a2f[mt][kk][1] = *reinterpret_cast<unsigned*>(&h1);
            a2f[mt][kk][2] = *reinterpret_cast<unsigned*>(&h2);
            a2f[mt][kk][3] = *reinterpret_cast<unsigned*>(&h3);
        }

    // ---- color layer 2 (HMMA) ----
    float acc2[2][8][4];
#pragma unroll
    for (int mt = 0; mt < 2; mt++)
#pragma unroll
        for (int nt = 0; nt < 8; nt++)
#pragma unroll
            for (int c = 0; c < 4; c++) acc2[mt][nt][c] = 0.f;
    {
        const unsigned char* bbase = sW4T + (g * W4_STRIDE_B) + 4 * t4;
#pragma unroll
        for (int nt = 0; nt < 8; nt++)
#pragma unroll
            for (int kk = 0; kk < 4; kk++) {
                const unsigned char* p = bbase + nt * 8 * W4_STRIDE_B + kk * 32;
                const unsigned b0v = *reinterpret_cast<const unsigned*>(p);
                const unsigned b1v = *reinterpret_cast<const unsigned*>(p + 16);
                MMA16816(acc2[0][nt], a2f[0][kk], b0v, b1v);
                MMA16816(acc2[1][nt], a2f[1][kk], b0v, b1v);
            }
    }

    // ---- head: +b4, relu, 64->3, lane-group reduce, sigmoid ----
    {
        float pr[4][3];
#pragma unroll
        for (int q = 0; q < 4; q++) { pr[q][0] = 0.f; pr[q][1] = 0.f; pr[q][2] = 0.f; }
#pragma unroll
        for (int nt = 0; nt < 8; nt++)
#pragma unroll
            for (int j = 0; j < 2; j++) {
                const int col = nt * 8 + 2 * t4 + j;
                const float b4v = sHW[OFF_B4 + col];
                const float w50 = sHW[OFF_W5 + col * 3 + 0];
                const float w51 = sHW[OFF_W5 + col * 3 + 1];
                const float w52 = sHW[OFF_W5 + col * 3 + 2];
#pragma unroll
                for (int mt = 0; mt < 2; mt++)
#pragma unroll
                    for (int hh = 0; hh < 2; hh++) {
                        const float hv = fmaxf(acc2[mt][nt][2 * hh + j] + b4v, 0.f);
                        pr[mt * 2 + hh][0] = fmaf(hv, w50, pr[mt * 2 + hh][0]);
                        pr[mt * 2 + hh][1] = fmaf(hv, w51, pr[mt * 2 + hh][1]);
                        pr[mt * 2 + hh][2] = fmaf(hv, w52, pr[mt * 2 + hh][2]);
                    }
            }
#pragma unroll
        for (int q = 0; q < 4; q++)
#pragma unroll
            for (int c = 0; c < 3; c++) {
                float v = pr[q][c];
                v += __shfl_xor_sync(0xffffffffu, v, 1);
                v += __shfl_xor_sync(0xffffffffu, v, 2);
                pr[q][c] = v;
            }
        if (t4 == 0) {
            const float b50 = sHW[OFF_B5 + 0], b51 = sHW[OFF_B5 + 1], b52 = sHW[OFF_B5 + 2];
#pragma unroll
            for (int mt = 0; mt < 2; mt++)
#pragma unroll
                for (int hh = 0; hh < 2; hh++) {
                    const int p = blockIdx.x * 128 + w * 32 + mt * 16 + hh * 8 + g;
                    const int q = mt * 2 + hh;
                    out[3 * p + 0] = 1.0f / (1.0f + __expf(-(pr[q][0] + b50)));
                    out[3 * p + 1] = 1.0f / (1.0f + __expf(-(pr[q][1] + b51)));
                    out[3 * p + 2] = 1.0f / (1.0f + __expf(-(pr[q][2] + b52)));
                }
        }
    }
}

extern "C" void kernel_launch(void* const* d_in, const int* in_sizes, int n_in,
                              void* d_out, int out_size)
{
    const float* pos    = (const float*)d_in[0];
    const float* dirv   = (const float*)d_in[1];
    const float* tables = (const float*)d_in[2];
    const float* W1 = (const float*)d_in[3];
    const float* B1 = (const float*)d_in[4];
    const float* W2 = (const float*)d_in[5];
    const float* B2 = (const float*)d_in[6];
    const float* W3 = (const float*)d_in[7];
    const float* B3 = (const float*)d_in[8];
    const float* W4 = (const float*)d_in[9];
    const float* B4 = (const float*)d_in[10];
    const float* W5 = (const float*)d_in[11];
    const float* B5 = (const float*)d_in[12];
    float* out = (float*)d_out;

    encode_kernel<<<NPTS / 256, 256>>>(pos, tables);
    mlp_hmma_kernel<<<NPTS / 128, 128>>>(
        dirv, W1, B1, W2, B2, W3, B3, W4, B4, W5, B5, out);
}

// round 13
// speedup vs baseline: 1.0701x; 1.0307x over previous
#include <cuda_runtime.h>
#include <cuda_fp16.h>
#include <math.h>

#define NPTS   524288
#define NLVL   16
#define TSIZE  (1 << 19)

// constants in shared (floats)
#define OFF_W5 0        // [64,3] 192
#define OFF_B5 192      // [3]
#define OFF_B4 195      // [64]
#define OFF_B2 259      // [16]
#define OFF_B1 275      // [64]
#define OFF_W2C15 339   // [64]  W2[:,15] fp32 (sigma column)
#define HW_TOTAL 403

#define A_STRIDE_B  144   // 72-half rows (A0 hi|lo); ldmatrix conflict-free
#define W1_STRIDE_B 80    // K=32 halfs padded to 40; banks 20g+t4 distinct
#define W2_STRIDE_B 144
#define W3_STRIDE_B 112
#define W4_STRIDE_B 144

#define SCALE_S 4096.0f
#define INV_S   (1.0f / 4096.0f)

typedef unsigned long long u64;

static __device__ __forceinline__ unsigned smem_u32(const void* p) {
    unsigned a;
    asm("{ .reg .u64 t; cvta.to.shared.u64 t, %1; cvt.u32.u64 %0, t; }" : "=r"(a) : "l"(p));
    return a;
}

#define LDMATRIX_X4(r0, r1, r2, r3, addr) \
    asm volatile("ldmatrix.sync.aligned.m8n8.x4.shared.b16 {%0,%1,%2,%3}, [%4];" \
        : "=r"(r0), "=r"(r1), "=r"(r2), "=r"(r3) : "r"(addr))

#define MMA16816(c, a, b0v, b1v) \
    asm volatile("mma.sync.aligned.m16n8k16.row.col.f32.f16.f16.f32 " \
        "{%0,%1,%2,%3}, {%4,%5,%6,%7}, {%8,%9}, {%0,%1,%2,%3};" \
        : "+f"((c)[0]), "+f"((c)[1]), "+f"((c)[2]), "+f"((c)[3]) \
        : "r"((a)[0]), "r"((a)[1]), "r"((a)[2]), "r"((a)[3]), "r"(b0v), "r"(b1v))

// feature scratch, chunk-major: g_feat[c * NPTS + n] holds feat[4c..4c+3] of point n
__device__ float4 g_feat[8 * NPTS];

// ======================= Kernel A: hash-grid encode =======================
__global__ __launch_bounds__(256, 4) void encode_kernel(
    const float* __restrict__ pos,
    const float* __restrict__ tables)
{
    const int i = blockIdx.x * 256 + threadIdx.x;

    const float px = pos[3 * i + 0];
    const float py = pos[3 * i + 1];
    const float pz = pos[3 * i + 2];

    float feat[32];
#pragma unroll
    for (int l = 0; l < NLVL; l++) {
        const float res = (float)(16 << l);      // exact: growth factor b == 2.0
        const float fx = px * res, fy = py * res, fz = pz * res;
        const float bx = floorf(fx), by = floorf(fy), bz = floorf(fz);
        const int ix = (int)bx, iy = (int)by, iz = (int)bz;
        const float wx = fx - bx, wy = fy - by, wz = fz - bz;
        const float2* __restrict__ tab =
            reinterpret_cast<const float2*>(tables) + (size_t)l * TSIZE;

        float f0 = 0.f, f1 = 0.f;
#pragma unroll
        for (int c = 0; c < 8; c++) {
            const int oi = (c >> 2) & 1, oj = (c >> 1) & 1, ok = c & 1;
            unsigned h = (unsigned)(ix + oi) * 1u
                       ^ (unsigned)(iy + oj) * 2654435761u
                       ^ (unsigned)(iz + ok) * 805459861u;
            h &= (TSIZE - 1);
            const float2 e = __ldg(tab + h);
            const float cw = (oi ? wx : 1.f - wx)
                           * (oj ? wy : 1.f - wy)
                           * (ok ? wz : 1.f - wz);
            f0 = fmaf(e.x, cw, f0);
            f1 = fmaf(e.y, cw, f1);
        }
        feat[2 * l + 0] = f0;
        feat[2 * l + 1] = f1;
    }

#pragma unroll
    for (int c = 0; c < 8; c++)
        g_feat[c * NPTS + i] = make_float4(feat[4 * c + 0], feat[4 * c + 1],
                                           feat[4 * c + 2], feat[4 * c + 3]);
}

// ============== Kernel B: all-HMMA MLPs, mt-serialized for occupancy ==============
__global__ __launch_bounds__(128, 5) void mlp_hmma_kernel(
    const float* __restrict__ dirv,
    const float* __restrict__ W1, const float* __restrict__ B1,
    const float* __restrict__ W2, const float* __restrict__ B2,
    const float* __restrict__ W3, const float* __restrict__ B3,
    const float* __restrict__ W4, const float* __restrict__ B4,
    const float* __restrict__ W5, const float* __restrict__ B5,
    float* __restrict__ out)
{
    __shared__ __align__(16) unsigned char sA[128 * A_STRIDE_B];     // A0 (hi|lo), later A1
    __shared__ __align__(16) unsigned char sW1T[64 * W1_STRIDE_B];   // W1^T, K=32
    __shared__ __align__(16) unsigned char sW2T[16 * W2_STRIDE_B];   // W2^T, K=64
    __shared__ __align__(16) unsigned char sW3T[64 * W3_STRIDE_B];   // W3^T + B3 col, K=48
    __shared__ __align__(16) unsigned char sW4T[64 * W4_STRIDE_B];   // W4^T, K=64
    __shared__ float sHW[HW_TOTAL];

    const int tid  = threadIdx.x;
    const int lane = tid & 31;
    const int w    = tid >> 5;
    const int g    = lane >> 2;
    const int t4   = lane & 3;

    const int i = blockIdx.x * 128 + tid;

    // ---- prefetch point data first (LDG in flight under staging) ----
    float4 fv4[8];
#pragma unroll
    for (int c = 0; c < 8; c++) fv4[c] = g_feat[c * NPTS + i];
    const float dx = dirv[3 * i + 0];
    const float dy = dirv[3 * i + 1];
    const float dz = dirv[3 * i + 2];

    // ---- stage constants + weights ----
    for (int t = tid; t < 192; t += 128) sHW[OFF_W5 + t] = W5[t];
    for (int t = tid; t < 3;   t += 128) sHW[OFF_B5 + t] = B5[t];
    for (int t = tid; t < 64;  t += 128) sHW[OFF_B4 + t] = B4[t];
    for (int t = tid; t < 16;  t += 128) sHW[OFF_B2 + t] = B2[t];
    for (int t = tid; t < 64;  t += 128) sHW[OFF_B1 + t] = B1[t];
    for (int t = tid; t < 64;  t += 128) sHW[OFF_W2C15 + t] = W2[t * 16 + 15];

    // W1^T rows [n][k], K=32 padded to 40
    for (int idx = tid; idx < 64 * 40; idx += 128) {
        const int n = idx / 40, k = idx % 40;
        const float v = (k < 32) ? W1[k * 64 + n] : 0.0f;
        *reinterpret_cast<__half*>(sW1T + n * W1_STRIDE_B + k * 2) = __float2half_rn(v);
    }
    // W2^T rows [n][k], K=64 padded to 72
    for (int idx = tid; idx < 16 * 72; idx += 128) {
        const int n = idx / 72, k = idx % 72;
        const float v = (k < 64) ? W2[k * 16 + n] : 0.0f;
        *reinterpret_cast<__half*>(sW2T + n * W2_STRIDE_B + k * 2) = __float2half_rn(v);
    }
    // W3^T rows: k<41 -> W3, k==41 -> B3, else 0
    for (int idx = tid; idx < 64 * 56; idx += 128) {
        const int n = idx / 56, k = idx % 56;
        float v = 0.0f;
        if (k < 41) v = W3[k * 64 + n];
        else if (k == 41) v = B3[n];
        *reinterpret_cast<__half*>(sW3T + n * W3_STRIDE_B + k * 2) = __float2half_rn(v);
    }
    // W4^T rows, K=64 padded to 72
    for (int idx = tid; idx < 64 * 72; idx += 128) {
        const int n = idx / 72, k = idx % 72;
        const float v = (k < 64) ? W4[k * 64 + n] : 0.0f;
        *reinterpret_cast<__half*>(sW4T + n * W4_STRIDE_B + k * 2) = __float2half_rn(v);
    }
    __syncthreads();

    const int m = lane >> 3, r = lane & 7;
    const unsigned sAbase = smem_u32(sA);

    // ---- stage A0 row: [fh(32) | fl(32) | 0..71], S=4096 scaling ----
    {
        __half v[72];
#pragma unroll
        for (int c = 0; c < 8; c++) {
            const float fvv[4] = { fv4[c].x, fv4[c].y, fv4[c].z, fv4[c].w };
#pragma unroll
            for (int j = 0; j < 4; j++) {
                const float fs = fvv[j] * SCALE_S;
                const __half fh = __float2half_rn(fs);
                v[4 * c + j]      = fh;
                v[32 + 4 * c + j] = __float2half_rn(fs - __half2float(fh));
            }
        }
#pragma unroll
        for (int k = 64; k < 72; k++) v[k] = __float2half_rn(0.0f);
        const uint4* vv = reinterpret_cast<const uint4*>(v);
        unsigned char* row = sA + tid * A_STRIDE_B;
#pragma unroll
        for (int q = 0; q < 9; q++)
            *reinterpret_cast<uint4*>(row + q * 16) = vv[q];
    }
    __syncwarp();

    // ================== per-mt-tile pipeline (serialized to save regs) ==================
#pragma unroll 1
    for (int mt = 0; mt < 2; mt++) {
        // ---- density layer 1: acc = 4096*feat . W1 (hi+lo exact A-side) ----
        unsigned af[4][4];
#pragma unroll
        for (int kk = 0; kk < 4; kk++) {
            const int row = w * 32 + mt * 16 + (m & 1) * 8 + r;
            const unsigned addr = sAbase + row * A_STRIDE_B + kk * 32 + (m >> 1) * 16;
            LDMATRIX_X4(af[kk][0], af[kk][1], af[kk][2], af[kk][3], addr);
        }
        float acc[8][4];
#pragma unroll
        for (int nt = 0; nt < 8; nt++)
#pragma unroll
            for (int c = 0; c < 4; c++) acc[nt][c] = 0.f;
        {
            const unsigned char* bbase = sW1T + (g * W1_STRIDE_B) + 4 * t4;
#pragma unroll
            for (int nt = 0; nt < 8; nt++) {
                const unsigned char* p0 = bbase + nt * 8 * W1_STRIDE_B;
                const unsigned b00 = *reinterpret_cast<const unsigned*>(p0);
                const unsigned b01 = *reinterpret_cast<const unsigned*>(p0 + 16);
                const unsigned b10 = *reinterpret_cast<const unsigned*>(p0 + 32);
                const unsigned b11 = *reinterpret_cast<const unsigned*>(p0 + 48);
                MMA16816(acc[nt], af[0], b00, b01);   // hi, k 0..15
                MMA16816(acc[nt], af[1], b10, b11);   // hi, k 16..31
                MMA16816(acc[nt], af[2], b00, b01);   // lo, same B
                MMA16816(acc[nt], af[3], b10, b11);
            }
        }

        // ---- epilogue: y = relu(acc/4096 + b1); fp32 sigma partials; pack frags ----
        unsigned ayf[4][4];
        float prS0 = 0.f, prS1 = 0.f;
#pragma unroll
        for (int kk = 0; kk < 4; kk++) {
            const float* cA = acc[2 * kk];
            const float* cB = acc[2 * kk + 1];
            const int colA = (2 * kk) * 8 + 2 * t4;
            const int colB = colA + 8;
            const float y00 = fmaxf(fmaf(cA[0], INV_S, sHW[OFF_B1 + colA]),     0.f);
            const float y01 = fmaxf(fmaf(cA[1], INV_S, sHW[OFF_B1 + colA + 1]), 0.f);
            const float y10 = fmaxf(fmaf(cA[2], INV_S, sHW[OFF_B1 + colA]),     0.f);
            const float y11 = fmaxf(fmaf(cA[3], INV_S, sHW[OFF_B1 + colA + 1]), 0.f);
            const float z00 = fmaxf(fmaf(cB[0], INV_S, sHW[OFF_B1 + colB]),     0.f);
            const float z01 = fmaxf(fmaf(cB[1], INV_S, sHW[OFF_B1 + colB + 1]), 0.f);
            const float z10 = fmaxf(fmaf(cB[2], INV_S, sHW[OFF_B1 + colB]),     0.f);
            const float z11 = fmaxf(fmaf(cB[3], INV_S, sHW[OFF_B1 + colB + 1]), 0.f);
            const float wA0 = sHW[OFF_W2C15 + colA], wA1 = sHW[OFF_W2C15 + colA + 1];
            const float wB0 = sHW[OFF_W2C15 + colB], wB1 = sHW[OFF_W2C15 + colB + 1];
            prS0 += y00 * wA0 + y01 * wA1 + z00 * wB0 + z01 * wB1;
            prS1 += y10 * wA0 + y11 * wA1 + z10 * wB0 + z11 * wB1;
            const __half2 h0 = __floats2half2_rn(y00, y01);
            const __half2 h1 = __floats2half2_rn(y10, y11);
            const __half2 h2 = __floats2half2_rn(z00, z01);
            const __half2 h3 = __floats2half2_rn(z10, z11);
            ayf[kk][0] = *reinterpret_cast<const unsigned*>(&h0);
            ayf[kk][1] = *reinterpret_cast<const unsigned*>(&h1);
            ayf[kk][2] = *reinterpret_cast<const unsigned*>(&h2);
            ayf[kk][3] = *reinterpret_cast<const unsigned*>(&h3);
        }

        // ---- sigma (fp32 path): reduce over t4 group ----
        prS0 += __shfl_xor_sync(0xffffffffu, prS0, 1);
        prS0 += __shfl_xor_sync(0xffffffffu, prS0, 2);
        prS1 += __shfl_xor_sync(0xffffffffu, prS1, 1);
        prS1 += __shfl_xor_sync(0xffffffffu, prS1, 2);
        if (t4 == 0) {
            const float b2s = sHW[OFF_B2 + 15];
            const int row0 = w * 32 + mt * 16 + g;
            out[3 * NPTS + blockIdx.x * 128 + row0]     = fmaxf(prS0 + b2s, 0.f);
            out[3 * NPTS + blockIdx.x * 128 + row0 + 8] = fmaxf(prS1 + b2s, 0.f);
        }

        // ---- density layer 2 (f16): den = y x W2 ----
        float accD2[2][4];
#pragma unroll
        for (int nt = 0; nt < 2; nt++)
#pragma unroll
            for (int c = 0; c < 4; c++) accD2[nt][c] = 0.f;
        {
            const unsigned char* bbase = sW2T + (g * W2_STRIDE_B) + 4 * t4;
#pragma unroll
            for (int nt = 0; nt < 2; nt++)
#pragma unroll
                for (int kk = 0; kk < 4; kk++) {
                    const unsigned char* p = bbase + nt * 8 * W2_STRIDE_B + kk * 32;
                    const unsigned b0v = *reinterpret_cast<const unsigned*>(p);
                    const unsigned b1v = *reinterpret_cast<const unsigned*>(p + 16);
                    MMA16816(accD2[nt], ayf[kk], b0v, b1v);
                }
        }

        // ---- den + B2 -> f16 into A1 cols 0..15 (this mt half's rows) ----
#pragma unroll
        for (int nt = 0; nt < 2; nt++)
#pragma unroll
            for (int ch = 0; ch < 2; ch++) {
                const int row = w * 32 + mt * 16 + ch * 8 + g;
                const int col0 = nt * 8 + 2 * t4;
                const float v0 = accD2[nt][2 * ch + 0] + sHW[OFF_B2 + col0];
                const float v1 = accD2[nt][2 * ch + 1] + sHW[OFF_B2 + col0 + 1];
                const __half2 hv = __floats2half2_rn(v0, v1);
                *reinterpret_cast<__half2*>(sA + row * A_STRIDE_B + col0 * 2) = hv;
            }

        // ---- SH (recomputed; only this half's lanes store) ----
        if ((lane >> 4) == mt) {
            const float x = dx, yv = dy, z = dz;
            const float x2 = x * x, y2 = yv * yv, z2 = z * z;
            const float xy = x * yv, xz = x * z, yz = yv * z;
            const float x4 = x2 * x2, y4 = y2 * y2;
            float sh[25];
            sh[0] = 0.28209479177387814f;
            const float c1 = 0.4886025119029199f;
            sh[1] = -c1 * yv; sh[2] = c1 * z; sh[3] = -c1 * x;
            const float sub = 0.31539156525252005f;
            const float v1 = 0.5462742152960396f, v2 = 1.0925484305920792f, v3 = 0.9461746957575601f;
            sh[4] = v2 * xy; sh[5] = -v2 * yz; sh[6] = v3 * z2 - sub; sh[7] = -v2 * xz;
            sh[8] = v1 * x2 - v1 * y2;
            const float w1c = 1.445305721320277f, w2c = 2.890611442640554f;
            const float w3c = 0.5900435899266435f, w4c = 0.304697199642977f;
            sh[9]  = -w3c * yv * (3.0f * x2 - y2);
            sh[10] =  w2c * xy * z;
            sh[11] =  w4c * yv * (1.5f - 7.5f * z2);
            sh[12] =  1.24392110863372f * z * (1.5f * z2 - 0.5f) - 0.497568443453487f * z;
            sh[13] =  w4c * x * (1.5f - 7.5f * z2);
            sh[14] =  w1c * z * (x2 - y2);
            sh[15] = -w3c * x * (x2 - 3.0f * y2);
            sh[16] =  2.5033429417967f * xy * (x2 - y2);
            sh[17] = -1.77013076977993f * yz * (3.0f * x2 - y2);
            sh[18] =  0.126156626101008f * xy * (52.5f * z2 - 7.5f);
            sh[19] =  0.267618617422916f * yv * (2.33333333333333f * z * (1.5f - 7.5f * z2) + 4.0f * z);
            sh[20] =  1.48099765681286f * z * (1.66666666666667f * z * (1.5f * z2 - 0.5f)
                                               - 0.666666666666667f * z)
                      - 0.952069922236839f * z2 + 0.317356640745613f;
            sh[21] =  0.267618617422916f * x * (2.33333333333333f * z * (1.5f - 7.5f * z2) + 4.0f * z);
            sh[22] =  0.063078313050504f * (x2 - y2) * (52.5f * z2 - 7.5f);
            sh[23] = -1.77013076977993f * xz * (x2 - 3.0f * y2);
            sh[24] = -3.75501441269506f * x2 * y2 + 0.625835735449176f * x4 + 0.625835735449176f * y4;

            __half vh[32];
#pragma unroll
            for (int k = 0; k < 25; k++) vh[k] = __float2half_rn(sh[k]);
            vh[25] = __float2half_rn(1.0f);   // col 41 = bias
#pragma unroll
            for (int k = 26; k < 32; k++) vh[k] = __float2half_rn(0.0f);
            const uint4* vv = reinterpret_cast<const uint4*>(vh);
            unsigned char* row = sA + tid * A_STRIDE_B + 32;
#pragma unroll
            for (int q = 0; q < 4; q++)
                *reinterpret_cast<uint4*>(row + q * 16) = vv[q];
        }
        __syncwarp();

        // ---- color layer 1: h1 = relu(A1 x W3b) ----
        unsigned a1f[3][4];
#pragma unroll
        for (int kk = 0; kk < 3; kk++) {
            const int row = w * 32 + mt * 16 + (m & 1) * 8 + r;
            const unsigned addr = sAbase + row * A_STRIDE_B + kk * 32 + (m >> 1) * 16;
            LDMATRIX_X4(a1f[kk][0], a1f[kk][1], a1f[kk][2], a1f[kk][3], addr);
        }
        float acc1[8][4];
#pragma unroll
        for (int nt = 0; nt < 8; nt++)
#pragma unroll
            for (int c = 0; c < 4; c++) acc1[nt][c] = 0.f;
        {
            const unsigned char* bbase = sW3T + (g * W3_STRIDE_B) + 4 * t4;
#pragma unroll
            for (int nt = 0; nt < 8; nt++)
#pragma unroll
                for (int kk = 0; kk < 3; kk++) {
                    const unsigned char* p = bbase + nt * 8 * W3_STRIDE_B + kk * 32;
                    const unsigned b0v = *reinterpret_cast<const unsigned*>(p);
                    const unsigned b1v = *reinterpret_cast<const unsigned*>(p + 16);
                    MMA16816(acc1[nt], a1f[kk], b0v, b1v);
                }
        }

        // ---- relu + repack -> A2 fragments ----
        unsigned a2f[4][4];
#pragma unroll
        for (int kk = 0; kk < 4; kk++) {
            const float* cA = acc1[2 * kk];
            const float* cB = acc1[2 * kk + 1];
            __half2 h0 = __floats2half2_rn(fmaxf(cA[0], 0.f), fmaxf(cA[1], 0.f));
            __half2 h1 = __floats2half2_rn(fmaxf(cA[2], 0.f), fmaxf(cA[3], 0.f));
            __half2 h2 = __floats2half2_rn(fmaxf(cB[0], 0.f), fmaxf(cB[1], 0.f));
            __half2 h3 = __floats2half2_rn(fmaxf(cB[2], 0.f), fmaxf(cB[3], 0.f));
            a2f[kk][0] = *reinterpret_cast<unsigned*>(&h0);
            a2f[kk][1] = *reinterpret_cast<unsigned*>(&h1);
            a2f[kk][2] = *reinterpret_cast<unsigned*>(&h2);
            a2f[kk][3] = *reinterpret_cast<unsigned*>(&h3);
        }

        // ---- color layer 2 ----
        float acc2[8][4];
#pragma unroll
        for (int nt = 0; nt < 8; nt++)
#pragma unroll
            for (int c = 0; c < 4; c++) acc2[nt][c] = 0.f;
        {
            const unsigned char* bbase = sW4T + (g * W4_STRIDE_B) + 4 * t4;
#pragma unroll
            for (int nt = 0; nt < 8; nt++)
#pragma unroll
                for (int kk = 0; kk < 4; kk++) {
                    const unsigned char* p = bbase + nt * 8 * W4_STRIDE_B + kk * 32;
                    const unsigned b0v = *reinterpret_cast<const unsigned*>(p);
                    const unsigned b1v = *reinterpret_cast<const unsigned*>(p + 16);
                    MMA16816(acc2[nt], a2f[kk], b0v, b1v);
                }
        }

        // ---- head: +b4, relu, 64->3, reduce, sigmoid ----
        {
            float pr[2][3];
#pragma unroll
            for (int q = 0; q < 2; q++) { pr[q][0] = 0.f; pr[q][1] = 0.f; pr[q][2] = 0.f; }
#pragma unroll
            for (int nt = 0; nt < 8; nt++)
#pragma unroll
                for (int j = 0; j < 2; j++) {
                    const int col = nt * 8 + 2 * t4 + j;
                    const float b4v = sHW[OFF_B4 + col];
                    const float w50 = sHW[OFF_W5 + col * 3 + 0];
                    const float w51 = sHW[OFF_W5 + col * 3 + 1];
                    const float w52 = sHW[OFF_W5 + col * 3 + 2];
#pragma unroll
                    for (int hh = 0; hh < 2; hh++) {
                        const float hv = fmaxf(acc2[nt][2 * hh + j] + b4v, 0.f);
                        pr[hh][0] = fmaf(hv, w50, pr[hh][0]);
                        pr[hh][1] = fmaf(hv, w51, pr[hh][1]);
                        pr[hh][2] = fmaf(hv, w52, pr[hh][2]);
                    }
                }
#pragma unroll
            for (int q = 0; q < 2; q++)
#pragma unroll
                for (int c = 0; c < 3; c++) {
                    float v = pr[q][c];
                    v += __shfl_xor_sync(0xffffffffu, v, 1);
                    v += __shfl_xor_sync(0xffffffffu, v, 2);
                    pr[q][c] = v;
                }
            if (t4 == 0) {
                const float b50 = sHW[OFF_B5 + 0], b51 = sHW[OFF_B5 + 1], b52 = sHW[OFF_B5 + 2];
#pragma unroll
                for (int hh = 0; hh < 2; hh++) {
                    const int p = blockIdx.x * 128 + w * 32 + mt * 16 + hh * 8 + g;
                    out[3 * p + 0] = 1.0f / (1.0f + __expf(-(pr[hh][0] + b50)));
                    out[3 * p + 1] = 1.0f / (1.0f + __expf(-(pr[hh][1] + b51)));
                    out[3 * p + 2] = 1.0f / (1.0f + __expf(-(pr[hh][2] + b52)));
                }
            }
        }
    }
}

extern "C" void kernel_launch(void* const* d_in, const int* in_sizes, int n_in,
                              void* d_out, int out_size)
{
    const float* pos    = (const float*)d_in[0];
    const float* dirv   = (const float*)d_in[1];
    const float* tables = (const float*)d_in[2];
    const float* W1 = (const float*)d_in[3];
    const float* B1 = (const float*)d_in[4];
    const float* W2 = (const float*)d_in[5];
    const float* B2 = (const float*)d_in[6];
    const float* W3 = (const float*)d_in[7];
    const float* B3 = (const float*)d_in[8];
    const float* W4 = (const float*)d_in[9];
    const float* B4 = (const float*)d_in[10];
    const float* W5 = (const float*)d_in[11];
    const float* B5 = (const float*)d_in[12];
    float* out = (float*)d_out;

    encode_kernel<<<NPTS / 256, 256>>>(pos, tables);
    mlp_hmma_kernel<<<NPTS / 128, 128>>>(
        dirv, W1, B1, W2, B2, W3, B3, W4, B4, W5, B5, out);
}

// round 14
// speedup vs baseline: 1.4526x; 1.3575x over previous
#include <cuda_runtime.h>
#include <cuda_fp16.h>
#include <math.h>

#define NPTS   524288
#define NLVL   16
#define TSIZE  (1 << 19)

#define PTS_PER_CTA 512
#define NTILES      4

// constants in shared (floats)
#define OFF_W5 0        // [64,3] 192
#define OFF_B5 192      // [3]
#define OFF_B4 195      // [64]
#define OFF_B2 259      // [16]
#define OFF_B1 275      // [64]
#define OFF_W2C15 339   // [64]  W2[:,15] fp32 (sigma column)
#define HW_TOTAL 403

#define A_STRIDE_B  144   // 72-half rows (A0 hi|lo); ldmatrix conflict-free
#define W1_STRIDE_B 80    // K=32 halfs padded to 40
#define W2_STRIDE_B 144
#define W3_STRIDE_B 112
#define W4_STRIDE_B 144

#define SCALE_S 4096.0f
#define INV_S   (1.0f / 4096.0f)

typedef unsigned long long u64;

static __device__ __forceinline__ unsigned smem_u32(const void* p) {
    unsigned a;
    asm("{ .reg .u64 t; cvta.to.shared.u64 t, %1; cvt.u32.u64 %0, t; }" : "=r"(a) : "l"(p));
    return a;
}

#define LDMATRIX_X4(r0, r1, r2, r3, addr) \
    asm volatile("ldmatrix.sync.aligned.m8n8.x4.shared.b16 {%0,%1,%2,%3}, [%4];" \
        : "=r"(r0), "=r"(r1), "=r"(r2), "=r"(r3) : "r"(addr))

#define MMA16816(c, a, b0v, b1v) \
    asm volatile("mma.sync.aligned.m16n8k16.row.col.f32.f16.f16.f32 " \
        "{%0,%1,%2,%3}, {%4,%5,%6,%7}, {%8,%9}, {%0,%1,%2,%3};" \
        : "+f"((c)[0]), "+f"((c)[1]), "+f"((c)[2]), "+f"((c)[3]) \
        : "r"((a)[0]), "r"((a)[1]), "r"((a)[2]), "r"((a)[3]), "r"(b0v), "r"(b1v))

// feature scratch, chunk-major: g_feat[c * NPTS + n] holds feat[4c..4c+3] of point n
__device__ float4 g_feat[8 * NPTS];

// ======================= Kernel A: hash-grid encode =======================
__global__ __launch_bounds__(256, 3) void encode_kernel(
    const float* __restrict__ pos,
    const float* __restrict__ tables)
{
    const int i = blockIdx.x * 256 + threadIdx.x;

    const float px = pos[3 * i + 0];
    const float py = pos[3 * i + 1];
    const float pz = pos[3 * i + 2];

    float feat[32];
#pragma unroll
    for (int l = 0; l < NLVL; l++) {
        const float res = (float)(16 << l);      // exact: growth factor b == 2.0
        const float fx = px * res, fy = py * res, fz = pz * res;
        const float bx = floorf(fx), by = floorf(fy), bz = floorf(fz);
        const int ix = (int)bx, iy = (int)by, iz = (int)bz;
        const float wx = fx - bx, wy = fy - by, wz = fz - bz;
        const float2* __restrict__ tab =
            reinterpret_cast<const float2*>(tables) + (size_t)l * TSIZE;

        float f0 = 0.f, f1 = 0.f;
#pragma unroll
        for (int c = 0; c < 8; c++) {
            const int oi = (c >> 2) & 1, oj = (c >> 1) & 1, ok = c & 1;
            unsigned h = (unsigned)(ix + oi) * 1u
                       ^ (unsigned)(iy + oj) * 2654435761u
                       ^ (unsigned)(iz + ok) * 805459861u;
            h &= (TSIZE - 1);
            const float2 e = __ldg(tab + h);
            const float cw = (oi ? wx : 1.f - wx)
                           * (oj ? wy : 1.f - wy)
                           * (ok ? wz : 1.f - wz);
            f0 = fmaf(e.x, cw, f0);
            f1 = fmaf(e.y, cw, f1);
        }
        feat[2 * l + 0] = f0;
        feat[2 * l + 1] = f1;
    }

#pragma unroll
    for (int c = 0; c < 8; c++)
        g_feat[c * NPTS + i] = make_float4(feat[4 * c + 0], feat[4 * c + 1],
                                           feat[4 * c + 2], feat[4 * c + 3]);
}

// ============== Kernel B: all-HMMA MLPs, 512 pts/CTA, mt-serialized ==============
__global__ __launch_bounds__(128, 5) void mlp_hmma_kernel(
    const float* __restrict__ dirv,
    const float* __restrict__ W1, const float* __restrict__ B1,
    const float* __restrict__ W2, const float* __restrict__ B2,
    const float* __restrict__ W3, const float* __restrict__ B3,
    const float* __restrict__ W4, const float* __restrict__ B4,
    const float* __restrict__ W5, const float* __restrict__ B5,
    float* __restrict__ out)
{
    __shared__ __align__(16) unsigned char sA[128 * A_STRIDE_B];     // A0 (hi|lo), later A1
    __shared__ __align__(16) unsigned char sW1T[64 * W1_STRIDE_B];   // W1^T, K=32
    __shared__ __align__(16) unsigned char sW2T[16 * W2_STRIDE_B];   // W2^T, K=64
    __shared__ __align__(16) unsigned char sW3T[64 * W3_STRIDE_B];   // W3^T + B3 col, K=48
    __shared__ __align__(16) unsigned char sW4T[64 * W4_STRIDE_B];   // W4^T, K=64
    __shared__ float sHW[HW_TOTAL];

    const int tid  = threadIdx.x;
    const int lane = tid & 31;
    const int w    = tid >> 5;
    const int g    = lane >> 2;
    const int t4   = lane & 3;

    // ---- stage constants + weights (once per CTA, amortized over 512 pts) ----
    for (int t = tid; t < 192; t += 128) sHW[OFF_W5 + t] = W5[t];
    for (int t = tid; t < 3;   t += 128) sHW[OFF_B5 + t] = B5[t];
    for (int t = tid; t < 64;  t += 128) sHW[OFF_B4 + t] = B4[t];
    for (int t = tid; t < 16;  t += 128) sHW[OFF_B2 + t] = B2[t];
    for (int t = tid; t < 64;  t += 128) sHW[OFF_B1 + t] = B1[t];
    for (int t = tid; t < 64;  t += 128) sHW[OFF_W2C15 + t] = W2[t * 16 + 15];

    for (int idx = tid; idx < 64 * 40; idx += 128) {
        const int n = idx / 40, k = idx % 40;
        const float v = (k < 32) ? W1[k * 64 + n] : 0.0f;
        *reinterpret_cast<__half*>(sW1T + n * W1_STRIDE_B + k * 2) = __float2half_rn(v);
    }
    for (int idx = tid; idx < 16 * 72; idx += 128) {
        const int n = idx / 72, k = idx % 72;
        const float v = (k < 64) ? W2[k * 16 + n] : 0.0f;
        *reinterpret_cast<__half*>(sW2T + n * W2_STRIDE_B + k * 2) = __float2half_rn(v);
    }
    for (int idx = tid; idx < 64 * 56; idx += 128) {
        const int n = idx / 56, k = idx % 56;
        float v = 0.0f;
        if (k < 41) v = W3[k * 64 + n];
        else if (k == 41) v = B3[n];
        *reinterpret_cast<__half*>(sW3T + n * W3_STRIDE_B + k * 2) = __float2half_rn(v);
    }
    for (int idx = tid; idx < 64 * 72; idx += 128) {
        const int n = idx / 72, k = idx % 72;
        const float v = (k < 64) ? W4[k * 64 + n] : 0.0f;
        *reinterpret_cast<__half*>(sW4T + n * W4_STRIDE_B + k * 2) = __float2half_rn(v);
    }
    __syncthreads();

    const int m = lane >> 3, r = lane & 7;
    const unsigned sAbase = smem_u32(sA);

#pragma unroll 1
    for (int tile = 0; tile < NTILES; tile++) {
        const int base = blockIdx.x * PTS_PER_CTA + tile * 128;
        const int i = base + tid;

        // ---- load point data ----
        float4 fv4[8];
#pragma unroll
        for (int c = 0; c < 8; c++) fv4[c] = g_feat[c * NPTS + i];
        const float dx = dirv[3 * i + 0];
        const float dy = dirv[3 * i + 1];
        const float dz = dirv[3 * i + 2];

        // ---- stage A0 row: [fh(32) | fl(32) | 0..71], S=4096 scaling ----
        {
            __half v[72];
#pragma unroll
            for (int c = 0; c < 8; c++) {
                const float fvv[4] = { fv4[c].x, fv4[c].y, fv4[c].z, fv4[c].w };
#pragma unroll
                for (int j = 0; j < 4; j++) {
                    const float fs = fvv[j] * SCALE_S;
                    const __half fh = __float2half_rn(fs);
                    v[4 * c + j]      = fh;
                    v[32 + 4 * c + j] = __float2half_rn(fs - __half2float(fh));
                }
            }
#pragma unroll
            for (int k = 64; k < 72; k++) v[k] = __float2half_rn(0.0f);
            const uint4* vv = reinterpret_cast<const uint4*>(v);
            unsigned char* row = sA + tid * A_STRIDE_B;
#pragma unroll
            for (int q = 0; q < 9; q++)
                *reinterpret_cast<uint4*>(row + q * 16) = vv[q];
        }
        __syncwarp();

        // ================== per-mt-tile pipeline ==================
#pragma unroll 1
        for (int mt = 0; mt < 2; mt++) {
            // ---- density layer 1: acc = 4096*feat . W1 (hi+lo exact A-side) ----
            unsigned af[4][4];
#pragma unroll
            for (int kk = 0; kk < 4; kk++) {
                const int row = w * 32 + mt * 16 + (m & 1) * 8 + r;
                const unsigned addr = sAbase + row * A_STRIDE_B + kk * 32 + (m >> 1) * 16;
                LDMATRIX_X4(af[kk][0], af[kk][1], af[kk][2], af[kk][3], addr);
            }
            float acc[8][4];
#pragma unroll
            for (int nt = 0; nt < 8; nt++)
#pragma unroll
                for (int c = 0; c < 4; c++) acc[nt][c] = 0.f;
            {
                const unsigned char* bbase = sW1T + (g * W1_STRIDE_B) + 4 * t4;
#pragma unroll
                for (int nt = 0; nt < 8; nt++) {
                    const unsigned char* p0 = bbase + nt * 8 * W1_STRIDE_B;
                    const unsigned b00 = *reinterpret_cast<const unsigned*>(p0);
                    const unsigned b01 = *reinterpret_cast<const unsigned*>(p0 + 16);
                    const unsigned b10 = *reinterpret_cast<const unsigned*>(p0 + 32);
                    const unsigned b11 = *reinterpret_cast<const unsigned*>(p0 + 48);
                    MMA16816(acc[nt], af[0], b00, b01);
                    MMA16816(acc[nt], af[1], b10, b11);
                    MMA16816(acc[nt], af[2], b00, b01);
                    MMA16816(acc[nt], af[3], b10, b11);
                }
            }

            // ---- epilogue: y = relu(acc/4096 + b1); sigma partials; pack frags ----
            unsigned ayf[4][4];
            float prS0 = 0.f, prS1 = 0.f;
#pragma unroll
            for (int kk = 0; kk < 4; kk++) {
                const float* cA = acc[2 * kk];
                const float* cB = acc[2 * kk + 1];
                const int colA = (2 * kk) * 8 + 2 * t4;
                const int colB = colA + 8;
                const float y00 = fmaxf(fmaf(cA[0], INV_S, sHW[OFF_B1 + colA]),     0.f);
                const float y01 = fmaxf(fmaf(cA[1], INV_S, sHW[OFF_B1 + colA + 1]), 0.f);
                const float y10 = fmaxf(fmaf(cA[2], INV_S, sHW[OFF_B1 + colA]),     0.f);
                const float y11 = fmaxf(fmaf(cA[3], INV_S, sHW[OFF_B1 + colA + 1]), 0.f);
                const float z00 = fmaxf(fmaf(cB[0], INV_S, sHW[OFF_B1 + colB]),     0.f);
                const float z01 = fmaxf(fmaf(cB[1], INV_S, sHW[OFF_B1 + colB + 1]), 0.f);
                const float z10 = fmaxf(fmaf(cB[2], INV_S, sHW[OFF_B1 + colB]),     0.f);
                const float z11 = fmaxf(fmaf(cB[3], INV_S, sHW[OFF_B1 + colB + 1]), 0.f);
                const float wA0 = sHW[OFF_W2C15 + colA], wA1 = sHW[OFF_W2C15 + colA + 1];
                const float wB0 = sHW[OFF_W2C15 + colB], wB1 = sHW[OFF_W2C15 + colB + 1];
                prS0 += y00 * wA0 + y01 * wA1 + z00 * wB0 + z01 * wB1;
                prS1 += y10 * wA0 + y11 * wA1 + z10 * wB0 + z11 * wB1;
                const __half2 h0 = __floats2half2_rn(y00, y01);
                const __half2 h1 = __floats2half2_rn(y10, y11);
                const __half2 h2 = __floats2half2_rn(z00, z01);
                const __half2 h3 = __floats2half2_rn(z10, z11);
                ayf[kk][0] = *reinterpret_cast<const unsigned*>(&h0);
                ayf[kk][1] = *reinterpret_cast<const unsigned*>(&h1);
                ayf[kk][2] = *reinterpret_cast<const unsigned*>(&h2);
                ayf[kk][3] = *reinterpret_cast<const unsigned*>(&h3);
            }

            // ---- sigma (fp32 path) ----
            prS0 += __shfl_xor_sync(0xffffffffu, prS0, 1);
            prS0 += __shfl_xor_sync(0xffffffffu, prS0, 2);
            prS1 += __shfl_xor_sync(0xffffffffu, prS1, 1);
            prS1 += __shfl_xor_sync(0xffffffffu, prS1, 2);
            if (t4 == 0) {
                const float b2s = sHW[OFF_B2 + 15];
                const int row0 = w * 32 + mt * 16 + g;
                out[3 * NPTS + base + row0]     = fmaxf(prS0 + b2s, 0.f);
                out[3 * NPTS + base + row0 + 8] = fmaxf(prS1 + b2s, 0.f);
            }

            // ---- density layer 2 (f16): den = y x W2 ----
            float accD2[2][4];
#pragma unroll
            for (int nt = 0; nt < 2; nt++)
#pragma unroll
                for (int c = 0; c < 4; c++) accD2[nt][c] = 0.f;
            {
                const unsigned char* bbase = sW2T + (g * W2_STRIDE_B) + 4 * t4;
#pragma unroll
                for (int nt = 0; nt < 2; nt++)
#pragma unroll
                    for (int kk = 0; kk < 4; kk++) {
                        const unsigned char* p = bbase + nt * 8 * W2_STRIDE_B + kk * 32;
                        const unsigned b0v = *reinterpret_cast<const unsigned*>(p);
                        const unsigned b1v = *reinterpret_cast<const unsigned*>(p + 16);
                        MMA16816(accD2[nt], ayf[kk], b0v, b1v);
                    }
            }

            // ---- den + B2 -> f16 into A1 cols 0..15 ----
#pragma unroll
            for (int nt = 0; nt < 2; nt++)
#pragma unroll
                for (int ch = 0; ch < 2; ch++) {
                    const int row = w * 32 + mt * 16 + ch * 8 + g;
                    const int col0 = nt * 8 + 2 * t4;
                    const float v0 = accD2[nt][2 * ch + 0] + sHW[OFF_B2 + col0];
                    const float v1 = accD2[nt][2 * ch + 1] + sHW[OFF_B2 + col0 + 1];
                    const __half2 hv = __floats2half2_rn(v0, v1);
                    *reinterpret_cast<__half2*>(sA + row * A_STRIDE_B + col0 * 2) = hv;
                }

            // ---- SH (recomputed; only this half's lanes store) ----
            if ((lane >> 4) == mt) {
                const float x = dx, yv = dy, z = dz;
                const float x2 = x * x, y2 = yv * yv, z2 = z * z;
                const float xy = x * yv, xz = x * z, yz = yv * z;
                const float x4 = x2 * x2, y4 = y2 * y2;
                float sh[25];
                sh[0] = 0.28209479177387814f;
                const float c1 = 0.4886025119029199f;
                sh[1] = -c1 * yv; sh[2] = c1 * z; sh[3] = -c1 * x;
                const float sub = 0.31539156525252005f;
                const float v1 = 0.5462742152960396f, v2 = 1.0925484305920792f, v3 = 0.9461746957575601f;
                sh[4] = v2 * xy; sh[5] = -v2 * yz; sh[6] = v3 * z2 - sub; sh[7] = -v2 * xz;
                sh[8] = v1 * x2 - v1 * y2;
                const float w1c = 1.445305721320277f, w2c = 2.890611442640554f;
                const float w3c = 0.5900435899266435f, w4c = 0.304697199642977f;
                sh[9]  = -w3c * yv * (3.0f * x2 - y2);
                sh[10] =  w2c * xy * z;
                sh[11] =  w4c * yv * (1.5f - 7.5f * z2);
                sh[12] =  1.24392110863372f * z * (1.5f * z2 - 0.5f) - 0.497568443453487f * z;
                sh[13] =  w4c * x * (1.5f - 7.5f * z2);
                sh[14] =  w1c * z * (x2 - y2);
                sh[15] = -w3c * x * (x2 - 3.0f * y2);
                sh[16] =  2.5033429417967f * xy * (x2 - y2);
                sh[17] = -1.77013076977993f * yz * (3.0f * x2 - y2);
                sh[18] =  0.126156626101008f * xy * (52.5f * z2 - 7.5f);
                sh[19] =  0.267618617422916f * yv * (2.33333333333333f * z * (1.5f - 7.5f * z2) + 4.0f * z);
                sh[20] =  1.48099765681286f * z * (1.66666666666667f * z * (1.5f * z2 - 0.5f)
                                                   - 0.666666666666667f * z)
                          - 0.952069922236839f * z2 + 0.317356640745613f;
                sh[21] =  0.267618617422916f * x * (2.33333333333333f * z * (1.5f - 7.5f * z2) + 4.0f * z);
                sh[22] =  0.063078313050504f * (x2 - y2) * (52.5f * z2 - 7.5f);
                sh[23] = -1.77013076977993f * xz * (x2 - 3.0f * y2);
                sh[24] = -3.75501441269506f * x2 * y2 + 0.625835735449176f * x4 + 0.625835735449176f * y4;

                __half vh[32];
#pragma unroll
                for (int k = 0; k < 25; k++) vh[k] = __float2half_rn(sh[k]);
                vh[25] = __float2half_rn(1.0f);   // col 41 = bias
#pragma unroll
                for (int k = 26; k < 32; k++) vh[k] = __float2half_rn(0.0f);
                const uint4* vv = reinterpret_cast<const uint4*>(vh);
                unsigned char* row = sA + tid * A_STRIDE_B + 32;
#pragma unroll
                for (int q = 0; q < 4; q++)
                    *reinterpret_cast<uint4*>(row + q * 16) = vv[q];
            }
            __syncwarp();

            // ---- color layer 1: h1 = relu(A1 x W3b) ----
            unsigned a1f[3][4];
#pragma unroll
            for (int kk = 0; kk < 3; kk++) {
                const int row = w * 32 + mt * 16 + (m & 1) * 8 + r;
                const unsigned addr = sAbase + row * A_STRIDE_B + kk * 32 + (m >> 1) * 16;
                LDMATRIX_X4(a1f[kk][0], a1f[kk][1], a1f[kk][2], a1f[kk][3], addr);
            }
            float acc1[8][4];
#pragma unroll
            for (int nt = 0; nt < 8; nt++)
#pragma unroll
                for (int c = 0; c < 4; c++) acc1[nt][c] = 0.f;
            {
                const unsigned char* bbase = sW3T + (g * W3_STRIDE_B) + 4 * t4;
#pragma unroll
                for (int nt = 0; nt < 8; nt++)
#pragma unroll
                    for (int kk = 0; kk < 3; kk++) {
                        const unsigned char* p = bbase + nt * 8 * W3_STRIDE_B + kk * 32;
                        const unsigned b0v = *reinterpret_cast<const unsigned*>(p);
                        const unsigned b1v = *reinterpret_cast<const unsigned*>(p + 16);
                        MMA16816(acc1[nt], a1f[kk], b0v, b1v);
                    }
            }

            // ---- relu + repack -> A2 fragments ----
            unsigned a2f[4][4];
#pragma unroll
            for (int kk = 0; kk < 4; kk++) {
                const float* cA = acc1[2 * kk];
                const float* cB = acc1[2 * kk + 1];
                __half2 h0 = __floats2half2_rn(fmaxf(cA[0], 0.f), fmaxf(cA[1], 0.f));
                __half2 h1 = __floats2half2_rn(fmaxf(cA[2], 0.f), fmaxf(cA[3], 0.f));
                __half2 h2 = __floats2half2_rn(fmaxf(cB[0], 0.f), fmaxf(cB[1], 0.f));
                __half2 h3 = __floats2half2_rn(fmaxf(cB[2], 0.f), fmaxf(cB[3], 0.f));
                a2f[kk][0] = *reinterpret_cast<unsigned*>(&h0);
                a2f[kk][1] = *reinterpret_cast<unsigned*>(&h1);
                a2f[kk][2] = *reinterpret_cast<unsigned*>(&h2);
                a2f[kk][3] = *reinterpret_cast<unsigned*>(&h3);
            }

            // ---- color layer 2 ----
            float acc2[8][4];
#pragma unroll
            for (int nt = 0; nt < 8; nt++)
#pragma unroll
                for (int c = 0; c < 4; c++) acc2[nt][c] = 0.f;
            {
                const unsigned char* bbase = sW4T + (g * W4_STRIDE_B) + 4 * t4;
#pragma unroll
                for (int nt = 0; nt < 8; nt++)
#pragma unroll
                    for (int kk = 0; kk < 4; kk++) {
                        const unsigned char* p = bbase + nt * 8 * W4_STRIDE_B + kk * 32;
                        const unsigned b0v = *reinterpret_cast<const unsigned*>(p);
                        const unsigned b1v = *reinterpret_cast<const unsigned*>(p + 16);
                        MMA16816(acc2[nt], a2f[kk], b0v, b1v);
                    }
            }

            // ---- head: +b4, relu, 64->3, reduce, sigmoid ----
            {
                float pr[2][3];
#pragma unroll
                for (int q = 0; q < 2; q++) { pr[q][0] = 0.f; pr[q][1] = 0.f; pr[q][2] = 0.f; }
#pragma unroll
                for (int nt = 0; nt < 8; nt++)
#pragma unroll
                    for (int j = 0; j < 2; j++) {
                        const int col = nt * 8 + 2 * t4 + j;
                        const float b4v = sHW[OFF_B4 + col];
                        const float w50 = sHW[OFF_W5 + col * 3 + 0];
                        const float w51 = sHW[OFF_W5 + col * 3 + 1];
                        const float w52 = sHW[OFF_W5 + col * 3 + 2];
#pragma unroll
                        for (int hh = 0; hh < 2; hh++) {
                            const float hv = fmaxf(acc2[nt][2 * hh + j] + b4v, 0.f);
                            pr[hh][0] = fmaf(hv, w50, pr[hh][0]);
                            pr[hh][1] = fmaf(hv, w51, pr[hh][1]);
                            pr[hh][2] = fmaf(hv, w52, pr[hh][2]);
                        }
                    }
#pragma unroll
                for (int q = 0; q < 2; q++)
#pragma unroll
                    for (int c = 0; c < 3; c++) {
                        float v = pr[q][c];
                        v += __shfl_xor_sync(0xffffffffu, v, 1);
                        v += __shfl_xor_sync(0xffffffffu, v, 2);
                        pr[q][c] = v;
                    }
                if (t4 == 0) {
                    const float b50 = sHW[OFF_B5 + 0], b51 = sHW[OFF_B5 + 1], b52 = sHW[OFF_B5 + 2];
#pragma unroll
                    for (int hh = 0; hh < 2; hh++) {
                        const int p = base + w * 32 + mt * 16 + hh * 8 + g;
                        out[3 * p + 0] = 1.0f / (1.0f + __expf(-(pr[hh][0] + b50)));
                        out[3 * p + 1] = 1.0f / (1.0f + __expf(-(pr[hh][1] + b51)));
                        out[3 * p + 2] = 1.0f / (1.0f + __expf(-(pr[hh][2] + b52)));
                    }
                }
            }
        }
        __syncwarp();
    }
}

extern "C" void kernel_launch(void* const* d_in, const int* in_sizes, int n_in,
                              void* d_out, int out_size)
{
    const float* pos    = (const float*)d_in[0];
    const float* dirv   = (const float*)d_in[1];
    const float* tables = (const float*)d_in[2];
    const float* W1 = (const float*)d_in[3];
    const float* B1 = (const float*)d_in[4];
    const float* W2 = (const float*)d_in[5];
    const float* B2 = (const float*)d_in[6];
    const float* W3 = (const float*)d_in[7];
    const float* B3 = (const float*)d_in[8];
    const float* W4 = (const float*)d_in[9];
    const float* B4 = (const float*)d_in[10];
    const float* W5 = (const float*)d_in[11];
    const float* B5 = (const float*)d_in[12];
    float* out = (float*)d_out;

    encode_kernel<<<NPTS / 256, 256>>>(pos, tables);
    mlp_hmma_kernel<<<NPTS / PTS_PER_CTA, 128>>>(
        dirv, W1, B1, W2, B2, W3, B3, W4, B4, W5, B5, out);
}